// round 12
// baseline (speedup 1.0000x reference)
#include <cuda_runtime.h>
#include <cuda_fp16.h>
#include <cuda_bf16.h>
#include <cstdint>

// Problem constants (fixed by the benchmark)
#define NN   50000
#define EE   800000
#define DD   128
#define LL   3
#define GG   16
#define OUTD 2

#define LO_SCALE 8192.0f            // 2^13
#define LO_INV   1.220703125e-4f    // 2^-13

// ---------------- static device scratch (no allocation allowed) ----------------
// Activations: bf16 hi + int8 lo (lo = (x - bf16(x)) * 2^13). Decode is pure ALU.
// g_cnt/g_pool/g_pcnt rely on load-time zero-init for call 1; zero_tail_kernel
// re-zeros them at the end of every call for replays.
__device__ __nv_bfloat16 g_xh[2][2][(size_t)NN * DD];   // [pingpong][type]
__device__ int8_t        g_xl[2][2][(size_t)NN * DD];
__device__ int   g_cnt[2][NN];
__device__ int   g_rowptr[2][NN + 1];
__device__ int   g_cursor[2][NN];
__device__ int   g_csr[2][EE];
__device__ float g_pool[2][GG][DD];
__device__ int   g_pcnt[2][GG];
__device__ __half g_wT_hi[6 * 32768];   // [L*2][128][256] fp16 hi
__device__ __half g_wT_lo[6 * 32768];   // fp16 lo

// ---------------- small helpers ----------------
__device__ __forceinline__ uint32_t smem_u32(const void* p) {
    uint32_t a;
    asm("{ .reg .u64 t; cvta.to.shared.u64 t, %1; cvt.u32.u64 %0, t; }" : "=r"(a) : "l"(p));
    return a;
}
__device__ __forceinline__ void ldsm4(uint32_t* r, uint32_t addr) {
    asm volatile("ldmatrix.sync.aligned.m8n8.x4.shared.b16 {%0,%1,%2,%3}, [%4];"
                 : "=r"(r[0]), "=r"(r[1]), "=r"(r[2]), "=r"(r[3]) : "r"(addr));
}
__device__ __forceinline__ void mma16816(float* c, const uint32_t* a, const uint32_t* b) {
    asm volatile("mma.sync.aligned.m16n8k16.row.col.f32.f16.f16.f32 "
                 "{%0,%1,%2,%3}, {%4,%5,%6,%7}, {%8,%9}, {%0,%1,%2,%3};"
                 : "+f"(c[0]), "+f"(c[1]), "+f"(c[2]), "+f"(c[3])
                 : "r"(a[0]), "r"(a[1]), "r"(a[2]), "r"(a[3]), "r"(b[0]), "r"(b[1]));
}
// encode one value -> bf16 hi + int8 lo
__device__ __forceinline__ void encHL(float v, unsigned short* h, int* li) {
    __nv_bfloat16 b = __float2bfloat16(v);
    *h = *(unsigned short*)&b;
    int r = __float2int_rn((v - __bfloat162float(b)) * LO_SCALE);
    *li = min(127, max(-128, r));
}
// decode stored pair -> fp32 (ALU-only for hi; used where cvt cost is fine)
__device__ __forceinline__ float decHL(unsigned short h, int8_t l) {
    return __uint_as_float(((uint32_t)h) << 16) + (float)l * LO_INV;
}

// ---------------- setup kernel: count + weight prep + input conversion ----------------
#define CNT_BLOCKS  1024
#define WPREP_BLOCKS 64
#define CONV_BLOCKS 128

__global__ void setup_kernel(const int* __restrict__ dst0, const int* __restrict__ dst1,
                             int E,
                             const float* __restrict__ Wl, const float* __restrict__ Wr,
                             const float* __restrict__ x0, const float* __restrict__ x1,
                             int n) {
    if (blockIdx.x < CNT_BLOCKS) {
        int i = blockIdx.x * blockDim.x + threadIdx.x;
        int stride = CNT_BLOCKS * blockDim.x;
        for (; i < 2 * E; i += stride) {
            if (i < E) atomicAdd(&g_cnt[0][dst0[i]], 1);
            else       atomicAdd(&g_cnt[1][dst1[i - E]], 1);
        }
    } else if (blockIdx.x < CNT_BLOCKS + WPREP_BLOCKS) {
        int i = (blockIdx.x - CNT_BLOCKS) * blockDim.x + threadIdx.x;
        int stride = WPREP_BLOCKS * blockDim.x;
        for (int it = i; it < 6 * DD * DD; it += stride) {
            int lt = it >> 14;
            int rem = it & 16383;
            int nrow = rem >> 7;
            int k = rem & 127;
            size_t wb = (size_t)lt * DD * DD;
            size_t ob = (size_t)lt * 32768 + (size_t)nrow * 256;
#pragma unroll
            for (int m = 0; m < 2; m++) {
                const float* W = m ? Wr : Wl;
                float v = W[wb + (size_t)k * DD + nrow];
                __half h = __float2half_rn(v);
                __half l = __float2half_rn(v - __half2float(h));
                g_wT_hi[ob + m * DD + k] = h;
                g_wT_lo[ob + m * DD + k] = l;
            }
        }
    } else {
        // convert fp32 inputs -> bf16+int8 into ping 0
        int i = (blockIdx.x - CNT_BLOCKS - WPREP_BLOCKS) * blockDim.x + threadIdx.x;
        int stride = CONV_BLOCKS * blockDim.x;
        int pairs = n * DD / 2;
        for (int p = i; p < 2 * pairs; p += stride) {
            int t = (p >= pairs);
            int q = t ? p - pairs : p;
            float2 v = ((const float2*)(t ? x1 : x0))[q];
            unsigned short hx, hy; int lx, ly;
            encHL(v.x, &hx, &lx);
            encHL(v.y, &hy, &ly);
            *(uint32_t*)(&g_xh[0][t][(size_t)q * 2]) = (uint32_t)hx | ((uint32_t)hy << 16);
            *(unsigned short*)(&g_xl[0][t][(size_t)q * 2]) =
                (unsigned short)((lx & 0xff) | ((ly & 0xff) << 8));
        }
    }
}

// scan + cursor seed
__global__ void scan_both_kernel(int n) {
    __shared__ int part[1024];
    int ty = blockIdx.x;
    const int* cnt = g_cnt[ty];
    int* rowptr = g_rowptr[ty];
    int* cursor = g_cursor[ty];
    int t = threadIdx.x;
    int chunk = (n + 1023) / 1024;
    int beg = t * chunk;
    int end = min(beg + chunk, n);
    int s = 0;
    for (int i = beg; i < end; i++) s += cnt[i];
    part[t] = s;
    __syncthreads();
    for (int off = 1; off < 1024; off <<= 1) {
        int v = (t >= off) ? part[t - off] : 0;
        __syncthreads();
        part[t] += v;
        __syncthreads();
    }
    int run = (t == 0) ? 0 : part[t - 1];
    for (int i = beg; i < end; i++) {
        rowptr[i] = run;
        cursor[i] = run;
        run += cnt[i];
    }
    if (t == 0) rowptr[n] = part[1023];
}

__global__ void fill_both_kernel(const int* __restrict__ e0,
                                 const int* __restrict__ e1, int E) {
    int i = blockIdx.x * blockDim.x + threadIdx.x;
    int stride = gridDim.x * blockDim.x;
    for (; i < 2 * E; i += stride) {
        int t = (i >= E);
        const int* e = t ? e1 : e0;
        int j = t ? i - E : i;
        int d = e[E + j];
        int pos = atomicAdd(&g_cursor[t][d], 1);
        g_csr[t][pos] = e[j];
    }
}

// per-edge gather accumulate: bf16 hi (shift decode, fp32 acc) + int8 lo (int acc).
// All decode ops are 4-cyc ALU; no cvt in the chain.
#define GACC(aa, ii, h, l) do { \
    (aa).x += __uint_as_float((h).x << 16); \
    (aa).y += __uint_as_float((h).x & 0xffff0000u); \
    (aa).z += __uint_as_float((h).y << 16); \
    (aa).w += __uint_as_float((h).y & 0xffff0000u); \
    (ii).x += ((int)((l) << 24)) >> 24; \
    (ii).y += ((int)((l) << 16)) >> 24; \
    (ii).z += ((int)((l) <<  8)) >> 24; \
    (ii).w += ((int)(l)) >> 24; \
} while (0)

// ---------------- fused layer: gather(mean)->smem + split-fp16 MMA GEMM ----------------
#define AST   40
#define MST   132
#define SMEM_LAYER (128 * MST * 4 + 4 * 128 * AST * 2)   // 108544

__global__ __launch_bounds__(256, 2)
void layer_kernel(const __nv_bfloat16* __restrict__ xh, const int8_t* __restrict__ xl,
                  __nv_bfloat16* __restrict__ yh, int8_t* __restrict__ yl,
                  const __half* __restrict__ wHi, const __half* __restrict__ wLo,
                  const float* __restrict__ bias,   // [2][128]
                  int n, int tiles_per_type) {
    extern __shared__ __align__(16) char smem[];
    float* meanS = (float*)smem;
    __half* Ah = (__half*)(smem + 128 * MST * 4);
    __half* Al = Ah + 128 * AST;
    __half* Bh = Al + 128 * AST;
    __half* Bl = Bh + 128 * AST;

    int tid = threadIdx.x, wid = tid >> 5, lane = tid & 31;
    int bt = blockIdx.x / tiles_per_type;
    int tile = blockIdx.x - bt * tiles_per_type;
    int row0 = tile * 128;

    const __nv_bfloat16* xh_t = xh + (size_t)bt * NN * DD;
    const int8_t* xl_t = xl + (size_t)bt * NN * DD;
    __nv_bfloat16* yh_t = yh + (size_t)bt * NN * DD;
    int8_t* yl_t = yl + (size_t)bt * NN * DD;
    const int* rowptr = g_rowptr[bt];
    const int* csr = g_csr[bt];
    const __half* whi = wHi + (size_t)bt * 32768;
    const __half* wlo = wLo + (size_t)bt * 32768;
    const float* bias_t = bias + bt * DD;

    // ---- phase 1: gather mean into smem (fp32 hi acc + exact int lo acc) ----
    {
        const uint2* xh2 = (const uint2*)xh_t;       // 32 uint2 per row (4 bf16 each)
        const uint32_t* xl4 = (const uint32_t*)xl_t; // 32 uint per row (4 int8 each)
#pragma unroll 1
        for (int r = 0; r < 16; r++) {
            int lrow = wid * 16 + r;
            int node = row0 + lrow;
            float4 a0 = make_float4(0.f, 0.f, 0.f, 0.f);
            float4 a1 = a0;
            int4 i0 = make_int4(0, 0, 0, 0);
            int4 i1 = i0;
            float4 res = make_float4(0.f, 0.f, 0.f, 0.f);
            if (node < n) {
                int b = rowptr[node];
                int e = rowptr[node + 1];
                int j = b;
#pragma unroll 1
                for (; j + 2 <= e; j += 2) {
                    int s0 = __ldg(&csr[j]);
                    int s1 = __ldg(&csr[j + 1]);
                    uint2 h0 = __ldg(&xh2[(size_t)s0 * 32 + lane]);
                    uint32_t l0 = __ldg(&xl4[(size_t)s0 * 32 + lane]);
                    uint2 h1 = __ldg(&xh2[(size_t)s1 * 32 + lane]);
                    uint32_t l1 = __ldg(&xl4[(size_t)s1 * 32 + lane]);
                    GACC(a0, i0, h0, l0);
                    GACC(a1, i1, h1, l1);
                }
                if (j < e) {
                    int s0 = __ldg(&csr[j]);
                    uint2 h0 = __ldg(&xh2[(size_t)s0 * 32 + lane]);
                    uint32_t l0 = __ldg(&xl4[(size_t)s0 * 32 + lane]);
                    GACC(a0, i0, h0, l0);
                }
                float ic = 1.0f / (float)max(e - b, 1);
                res.x = (a0.x + a1.x + (float)(i0.x + i1.x) * LO_INV) * ic;
                res.y = (a0.y + a1.y + (float)(i0.y + i1.y) * LO_INV) * ic;
                res.z = (a0.z + a1.z + (float)(i0.z + i1.z) * LO_INV) * ic;
                res.w = (a0.w + a1.w + (float)(i0.w + i1.w) * LO_INV) * ic;
            }
            *(float4*)(meanS + lrow * MST + lane * 4) = res;
        }
    }
    __syncthreads();

    // ---- phase 2: GEMM C = [mean|x] @ W' (fp16-split, 3-product) ----
    int wm = wid & 3;
    int wn = wid >> 2;

    float acc[2][8][4];
#pragma unroll
    for (int a = 0; a < 2; a++)
#pragma unroll
        for (int b = 0; b < 8; b++)
#pragma unroll
            for (int c = 0; c < 4; c++) acc[a][b][c] = 0.f;

    uint32_t ahB = smem_u32(Ah), alB = smem_u32(Al);
    uint32_t bhB = smem_u32(Bh), blB = smem_u32(Bl);

    int a_row = wm * 32 + (lane & 7) + ((lane >> 3) & 1) * 8;
    int a_col = (lane >> 4) * 8;
    int b_row = wn * 64 + (lane & 7) + (lane >> 4) * 8;
    int b_col = ((lane >> 3) & 1) * 8;

    int frow = tid >> 1;
    int fcol = (tid & 1) * 16;

    for (int kb = 0; kb < 8; kb++) {
        // ---- fill A tile (source fp32 -> fp16 hi/lo split) ----
        {
            int kc = (kb & 3) * 32;
            int gr = row0 + frow;
            __half* ah = Ah + frow * AST + fcol;
            __half* al = Al + frow * AST + fcol;
#pragma unroll
            for (int i = 0; i < 4; i++) {
                float4 v;
                if (kb < 4) {
                    v = *(const float4*)(meanS + frow * MST + kc + fcol + i * 4);
                } else if (gr < n) {
                    // decode stored x: bf16 (exact shift) + int8*2^-13
                    const unsigned short* ph =
                        (const unsigned short*)(xh_t + (size_t)gr * DD + kc + fcol + i * 4);
                    const int8_t* pl = xl_t + (size_t)gr * DD + kc + fcol + i * 4;
                    uint2 hb = *(const uint2*)ph;
                    uint32_t lb = *(const uint32_t*)pl;
                    v.x = __uint_as_float(hb.x << 16)        + (float)(((int)(lb << 24)) >> 24) * LO_INV;
                    v.y = __uint_as_float(hb.x & 0xffff0000u) + (float)(((int)(lb << 16)) >> 24) * LO_INV;
                    v.z = __uint_as_float(hb.y << 16)        + (float)(((int)(lb << 8)) >> 24) * LO_INV;
                    v.w = __uint_as_float(hb.y & 0xffff0000u) + (float)(((int)lb) >> 24) * LO_INV;
                } else {
                    v = make_float4(0.f, 0.f, 0.f, 0.f);
                }
                __half hx = __float2half_rn(v.x), hy = __float2half_rn(v.y);
                __half hz = __float2half_rn(v.z), hw = __float2half_rn(v.w);
                *(half2*)(ah + i * 4)     = __halves2half2(hx, hy);
                *(half2*)(ah + i * 4 + 2) = __halves2half2(hz, hw);
                *(half2*)(al + i * 4)     = __halves2half2(
                    __float2half_rn(v.x - __half2float(hx)),
                    __float2half_rn(v.y - __half2float(hy)));
                *(half2*)(al + i * 4 + 2) = __halves2half2(
                    __float2half_rn(v.z - __half2float(hz)),
                    __float2half_rn(v.w - __half2float(hw)));
            }
        }
        // ---- fill B tile (pre-split fp16 weights) ----
        {
            int bn = tid >> 1;
            size_t goff = (size_t)bn * 256 + kb * 32 + fcol;
            const int4* gh = (const int4*)(whi + goff);
            const int4* gl = (const int4*)(wlo + goff);
            int4* sh = (int4*)(Bh + bn * AST + fcol);
            int4* sl = (int4*)(Bl + bn * AST + fcol);
            sh[0] = gh[0]; sh[1] = gh[1];
            sl[0] = gl[0]; sl[1] = gl[1];
        }
        __syncthreads();

#pragma unroll
        for (int ks = 0; ks < 2; ks++) {
            int k0 = ks * 16;
            uint32_t ah[2][4], al2[2][4], bf[16];
#pragma unroll
            for (int mt = 0; mt < 2; mt++)
                ldsm4(ah[mt], ahB + ((a_row + mt * 16) * AST + a_col + k0) * 2);
#pragma unroll
            for (int p = 0; p < 4; p++)
                ldsm4(&bf[p * 4], bhB + ((b_row + p * 16) * AST + b_col + k0) * 2);
#pragma unroll
            for (int mt = 0; mt < 2; mt++)
#pragma unroll
                for (int p = 0; p < 4; p++) {
                    mma16816(acc[mt][p * 2 + 0], ah[mt], &bf[p * 4 + 0]);
                    mma16816(acc[mt][p * 2 + 1], ah[mt], &bf[p * 4 + 2]);
                }
#pragma unroll
            for (int mt = 0; mt < 2; mt++)
                ldsm4(al2[mt], alB + ((a_row + mt * 16) * AST + a_col + k0) * 2);
#pragma unroll
            for (int mt = 0; mt < 2; mt++)
#pragma unroll
                for (int p = 0; p < 4; p++) {
                    mma16816(acc[mt][p * 2 + 0], al2[mt], &bf[p * 4 + 0]);
                    mma16816(acc[mt][p * 2 + 1], al2[mt], &bf[p * 4 + 2]);
                }
#pragma unroll
            for (int p = 0; p < 4; p++)
                ldsm4(&bf[p * 4], blB + ((b_row + p * 16) * AST + b_col + k0) * 2);
#pragma unroll
            for (int mt = 0; mt < 2; mt++)
#pragma unroll
                for (int p = 0; p < 4; p++) {
                    mma16816(acc[mt][p * 2 + 0], ah[mt], &bf[p * 4 + 0]);
                    mma16816(acc[mt][p * 2 + 1], ah[mt], &bf[p * 4 + 2]);
                }
        }
        __syncthreads();
    }

    // ---- epilogue: bias + relu -> bf16 + int8 stores ----
#pragma unroll
    for (int mt = 0; mt < 2; mt++) {
#pragma unroll
        for (int rr = 0; rr < 2; rr++) {
            int row = row0 + wm * 32 + mt * 16 + (lane >> 2) + rr * 8;
            if (row >= n) continue;
#pragma unroll
            for (int nt = 0; nt < 8; nt++) {
                int col = wn * 64 + nt * 8 + (lane & 3) * 2;
                float vx = fmaxf(acc[mt][nt][rr * 2 + 0] + __ldg(&bias_t[col + 0]), 0.f);
                float vy = fmaxf(acc[mt][nt][rr * 2 + 1] + __ldg(&bias_t[col + 1]), 0.f);
                unsigned short hx, hy; int lx, ly;
                encHL(vx, &hx, &lx);
                encHL(vy, &hy, &ly);
                *(uint32_t*)(yh_t + (size_t)row * DD + col) =
                    (uint32_t)hx | ((uint32_t)hy << 16);
                *(unsigned short*)(yl_t + (size_t)row * DD + col) =
                    (unsigned short)((lx & 0xff) | ((ly & 0xff) << 8));
            }
        }
    }
}

// ---------------- pooling + head ----------------
#define ROWS_PB 256
__global__ void pool_both_kernel(const __nv_bfloat16* __restrict__ xh,
                                 const int8_t* __restrict__ xl,
                                 const int* __restrict__ ba, const int* __restrict__ bb,
                                 int n, int pblocks) {
    int t = (blockIdx.x >= pblocks);
    int blk = t ? blockIdx.x - pblocks : blockIdx.x;
    const __nv_bfloat16* xh_t = xh + (size_t)t * NN * DD;
    const int8_t* xl_t = xl + (size_t)t * NN * DD;
    const int* batch = t ? bb : ba;
    float* pool = &g_pool[t][0][0];
    int* pcnt = g_pcnt[t];

    int c = threadIdx.x;
    int r0 = blk * ROWS_PB;
    if (r0 >= n) return;
    int r1 = min(r0 + ROWS_PB, n);
    float acc = 0.f;
    int cnt = 0;
    int gcur = batch[r0];
    for (int r = r0; r < r1; r++) {
        int g = batch[r];
        if (g != gcur) {
            atomicAdd(&pool[(size_t)gcur * DD + c], acc);
            if (c == 0) atomicAdd(&pcnt[gcur], cnt);
            acc = 0.f; cnt = 0; gcur = g;
        }
        unsigned short h = *(const unsigned short*)(xh_t + (size_t)r * DD + c);
        acc += decHL(h, xl_t[(size_t)r * DD + c]);
        cnt++;
    }
    atomicAdd(&pool[(size_t)gcur * DD + c], acc);
    if (c == 0) atomicAdd(&pcnt[gcur], cnt);
}

__global__ void final_kernel(const float* __restrict__ linW, const float* __restrict__ linb,
                             float* __restrict__ out) {
    int t32 = threadIdx.x;
    if (t32 >= GG * OUTD) return;
    int g = t32 / OUTD;
    int o = t32 % OUTD;
    float s = linb[o];
    for (int t = 0; t < 2; t++) {
        float ic = 1.0f / fmaxf((float)g_pcnt[t][g], 1.0f);
        const float* p = &g_pool[t][g][0];
        for (int c = 0; c < DD; c++)
            s += p[c] * ic * linW[(t * DD + c) * OUTD + o];
    }
    out[g * OUTD + o] = s;
}

__global__ void zero_tail_kernel() {
    int i = blockIdx.x * blockDim.x + threadIdx.x;
    int stride = gridDim.x * blockDim.x;
    int* cnt = &g_cnt[0][0];
    for (int j = i; j < 2 * NN; j += stride) cnt[j] = 0;
    float* pool = &g_pool[0][0][0];
    for (int j = i; j < 2 * GG * DD; j += stride) pool[j] = 0.f;
    int* pcnt = &g_pcnt[0][0];
    for (int j = i; j < 2 * GG; j += stride) pcnt[j] = 0;
}

// ---------------- launch ----------------
extern "C" void kernel_launch(void* const* d_in, const int* in_sizes, int n_in,
                              void* d_out, int out_size) {
    const float* x_void   = (const float*)d_in[0];
    const float* x_vessel = (const float*)d_in[1];
    const float* Wl   = (const float*)d_in[2];
    const float* bl   = (const float*)d_in[3];
    const float* Wr   = (const float*)d_in[4];
    const float* linW = (const float*)d_in[5];
    const float* linb = (const float*)d_in[6];
    const int* edge_void   = (const int*)d_in[7];
    const int* edge_vessel = (const int*)d_in[8];
    const int* batch_void   = (const int*)d_in[9];
    const int* batch_vessel = (const int*)d_in[10];

    const int n = in_sizes[9];
    const int E = in_sizes[7] / 2;

    __nv_bfloat16* xhP;
    int8_t* xlP;
    __half *whiP, *wloP;
    cudaGetSymbolAddress((void**)&xhP, g_xh);
    cudaGetSymbolAddress((void**)&xlP, g_xl);
    cudaGetSymbolAddress((void**)&whiP, g_wT_hi);
    cudaGetSymbolAddress((void**)&wloP, g_wT_lo);

    cudaFuncSetAttribute(layer_kernel,
                         cudaFuncAttributeMaxDynamicSharedMemorySize, SMEM_LAYER);

    // setup (3 launches)
    setup_kernel<<<CNT_BLOCKS + WPREP_BLOCKS + CONV_BLOCKS, 256>>>(
        edge_void + E, edge_vessel + E, E, Wl, Wr, x_void, x_vessel, n);
    scan_both_kernel<<<2, 1024>>>(n);
    fill_both_kernel<<<1024, 256>>>(edge_void, edge_vessel, E);

    const int tiles = (n + 127) / 128;
    const size_t PP = (size_t)2 * NN * DD;       // pingpong stride

    for (int l = 0; l < LL; l++) {
        int pin = l & 1;                         // 0,1,0
        int pout = 1 - pin;                      // 1,0,1
        layer_kernel<<<2 * tiles, 256, SMEM_LAYER>>>(
            xhP + pin * PP, xlP + pin * PP,
            xhP + pout * PP, xlP + pout * PP,
            whiP + (size_t)l * 2 * 32768, wloP + (size_t)l * 2 * 32768,
            bl + (size_t)l * 2 * DD, n, tiles);
    }

    // pooling reads ping 1 (output of layer 2)
    int pblocks = (n + ROWS_PB - 1) / ROWS_PB;
    pool_both_kernel<<<2 * pblocks, DD>>>(xhP + PP, xlP + PP,
                                          batch_void, batch_vessel, n, pblocks);
    final_kernel<<<1, 32>>>(linW, linb, (float*)d_out);
    zero_tail_kernel<<<64, 256>>>();
}

// round 14
// speedup vs baseline: 1.2406x; 1.2406x over previous
#include <cuda_runtime.h>
#include <cuda_fp16.h>
#include <cuda_bf16.h>
#include <cstdint>

// Problem constants (fixed by the benchmark)
#define NN   50000
#define EE   800000
#define DD   128
#define LL   3
#define GG   16
#define OUTD 2

// ---------------- static device scratch (no allocation allowed) ----------------
__device__ __nv_bfloat16 g_x[2][2][(size_t)NN * DD];   // [pingpong][type] activations
__device__ int   g_cnt[2][NN];
__device__ int   g_rowptr[2][NN + 1];
__device__ int   g_cursor[2][NN];
__device__ int   g_csr[2][EE];
__device__ float g_pool[2][GG][DD];
__device__ int   g_pcnt[2][GG];
__device__ __half g_wT_hi[6 * 32768];   // [L*2][128][256] fp16 hi
__device__ __half g_wT_lo[6 * 32768];   // fp16 lo

// ---------------- small helpers ----------------
__device__ __forceinline__ uint32_t smem_u32(const void* p) {
    uint32_t a;
    asm("{ .reg .u64 t; cvta.to.shared.u64 t, %1; cvt.u32.u64 %0, t; }" : "=r"(a) : "l"(p));
    return a;
}
__device__ __forceinline__ void ldsm4(uint32_t* r, uint32_t addr) {
    asm volatile("ldmatrix.sync.aligned.m8n8.x4.shared.b16 {%0,%1,%2,%3}, [%4];"
                 : "=r"(r[0]), "=r"(r[1]), "=r"(r[2]), "=r"(r[3]) : "r"(addr));
}
__device__ __forceinline__ void mma16816(float* c, const uint32_t* a, const uint32_t* b) {
    asm volatile("mma.sync.aligned.m16n8k16.row.col.f32.f16.f16.f32 "
                 "{%0,%1,%2,%3}, {%4,%5,%6,%7}, {%8,%9}, {%0,%1,%2,%3};"
                 : "+f"(c[0]), "+f"(c[1]), "+f"(c[2]), "+f"(c[3])
                 : "r"(a[0]), "r"(a[1]), "r"(a[2]), "r"(a[3]), "r"(b[0]), "r"(b[1]));
}
// pack two fp32 -> bf16x2 (low half = first arg)
__device__ __forceinline__ uint32_t bf2(float lo, float hi) {
    uint32_t r;
    asm("cvt.rn.bf16x2.f32 %0, %1, %2;" : "=r"(r) : "f"(hi), "f"(lo));
    return r;
}
// bf16-pair decode: pure ALU (shift / mask)
#define BACC(aa, h) do { \
    (aa).x += __uint_as_float((h).x << 16); \
    (aa).y += __uint_as_float((h).x & 0xffff0000u); \
    (aa).z += __uint_as_float((h).y << 16); \
    (aa).w += __uint_as_float((h).y & 0xffff0000u); \
} while (0)

// ---------------- setup kernels ----------------

__global__ void zero_all_kernel() {
    int i = blockIdx.x * blockDim.x + threadIdx.x;
    int stride = gridDim.x * blockDim.x;
    int* cnt = &g_cnt[0][0];
    for (int j = i; j < 2 * NN; j += stride) cnt[j] = 0;
    float* pool = &g_pool[0][0][0];
    for (int j = i; j < 2 * GG * DD; j += stride) pool[j] = 0.f;
    int* pcnt = &g_pcnt[0][0];
    for (int j = i; j < 2 * GG; j += stride) pcnt[j] = 0;
}

__global__ void count_both_kernel(const int* __restrict__ dst0,
                                  const int* __restrict__ dst1, int E) {
    int i = blockIdx.x * blockDim.x + threadIdx.x;
    int stride = gridDim.x * blockDim.x;
    for (; i < 2 * E; i += stride) {
        if (i < E) atomicAdd(&g_cnt[0][dst0[i]], 1);
        else       atomicAdd(&g_cnt[1][dst1[i - E]], 1);
    }
}

__global__ void scan_both_kernel(int n) {
    __shared__ int part[1024];
    int ty = blockIdx.x;
    const int* cnt = g_cnt[ty];
    int* rowptr = g_rowptr[ty];
    int* cursor = g_cursor[ty];
    int t = threadIdx.x;
    int chunk = (n + 1023) / 1024;
    int beg = t * chunk;
    int end = min(beg + chunk, n);
    int s = 0;
    for (int i = beg; i < end; i++) s += cnt[i];
    part[t] = s;
    __syncthreads();
    for (int off = 1; off < 1024; off <<= 1) {
        int v = (t >= off) ? part[t - off] : 0;
        __syncthreads();
        part[t] += v;
        __syncthreads();
    }
    int run = (t == 0) ? 0 : part[t - 1];
    for (int i = beg; i < end; i++) {
        rowptr[i] = run;
        cursor[i] = run;
        run += cnt[i];
    }
    if (t == 0) rowptr[n] = part[1023];
}

__global__ void fill_both_kernel(const int* __restrict__ e0,
                                 const int* __restrict__ e1, int E) {
    int i = blockIdx.x * blockDim.x + threadIdx.x;
    int stride = gridDim.x * blockDim.x;
    for (; i < 2 * E; i += stride) {
        int t = (i >= E);
        const int* e = t ? e1 : e0;
        int j = t ? i - E : i;
        int d = e[E + j];
        int pos = atomicAdd(&g_cursor[t][d], 1);
        g_csr[t][pos] = e[j];
    }
}

__global__ void wprep_all_kernel(const float* __restrict__ Wl,
                                 const float* __restrict__ Wr) {
    int lt = blockIdx.y;       // 0..5 = l*2+t
    int nrow = blockIdx.x;     // 0..127
    int k = threadIdx.x;       // 0..127
    size_t wb = (size_t)lt * DD * DD;
    size_t ob = (size_t)lt * 32768 + (size_t)nrow * 256;
#pragma unroll
    for (int m = 0; m < 2; m++) {
        const float* W = m ? Wr : Wl;
        float v = W[wb + (size_t)k * DD + nrow];
        __half h = __float2half_rn(v);
        __half l = __float2half_rn(v - __half2float(h));
        g_wT_hi[ob + m * DD + k] = h;
        g_wT_lo[ob + m * DD + k] = l;
    }
}

// convert fp32 inputs -> bf16 into ping 0
__global__ void conv_kernel(const float* __restrict__ x0, const float* __restrict__ x1,
                            int n) {
    int i = blockIdx.x * blockDim.x + threadIdx.x;
    int stride = gridDim.x * blockDim.x;
    int pairs = n * DD / 2;
    for (int p = i; p < 2 * pairs; p += stride) {
        int t = (p >= pairs);
        int q = t ? p - pairs : p;
        float2 v = ((const float2*)(t ? x1 : x0))[q];
        *(uint32_t*)(&g_x[0][t][(size_t)q * 2]) = bf2(v.x, v.y);
    }
}

// ---------------- fused layer: gather(mean)->smem + split-fp16 MMA GEMM ----------------
#define AST   40                     // padded GEMM tile stride (halfs), conflict-free
#define MST   132                    // mean smem stride (floats), conflict-free
#define SMEM_LAYER (128 * MST * 4 + 4 * 128 * AST * 2)   // 108544

__global__ __launch_bounds__(256, 2)
void layer_kernel(const __nv_bfloat16* __restrict__ xin, __nv_bfloat16* __restrict__ yout,
                  const __half* __restrict__ wHi, const __half* __restrict__ wLo,
                  const float* __restrict__ bias,   // [2][128]
                  int n, int tiles_per_type) {
    extern __shared__ __align__(16) char smem[];
    float* meanS = (float*)smem;
    __half* Ah = (__half*)(smem + 128 * MST * 4);
    __half* Al = Ah + 128 * AST;
    __half* Bh = Al + 128 * AST;
    __half* Bl = Bh + 128 * AST;

    int tid = threadIdx.x, wid = tid >> 5, lane = tid & 31;
    int bt = blockIdx.x / tiles_per_type;
    int tile = blockIdx.x - bt * tiles_per_type;
    int row0 = tile * 128;

    const __nv_bfloat16* xin_t = xin + (size_t)bt * NN * DD;
    __nv_bfloat16* yout_t = yout + (size_t)bt * NN * DD;
    const int* rowptr = g_rowptr[bt];
    const int* csr = g_csr[bt];
    const __half* whi = wHi + (size_t)bt * 32768;
    const __half* wlo = wLo + (size_t)bt * 32768;
    const float* bias_t = bias + bt * DD;

    // ---- phase 1: gather mean into smem (bf16 rows, single 8B/lane load/edge) ----
    {
        const uint2* x2 = (const uint2*)xin_t;   // 32 uint2 per row (4 bf16 each)
#pragma unroll 1
        for (int r = 0; r < 16; r++) {
            int lrow = wid * 16 + r;
            int node = row0 + lrow;
            float4 a0 = make_float4(0.f, 0.f, 0.f, 0.f);
            float4 a1 = a0;
            if (node < n) {
                int b = rowptr[node];
                int e = rowptr[node + 1];
                int j = b;
#pragma unroll 1
                for (; j + 1 < e; j += 2) {
                    int s0 = __ldg(&csr[j]);
                    int s1 = __ldg(&csr[j + 1]);
                    uint2 h0 = __ldg(&x2[(size_t)s0 * 32 + lane]);
                    uint2 h1 = __ldg(&x2[(size_t)s1 * 32 + lane]);
                    BACC(a0, h0);
                    BACC(a1, h1);
                }
                if (j < e) {
                    int s0 = __ldg(&csr[j]);
                    uint2 h0 = __ldg(&x2[(size_t)s0 * 32 + lane]);
                    BACC(a0, h0);
                }
                float ic = 1.0f / (float)max(e - b, 1);
                a0.x = (a0.x + a1.x) * ic;
                a0.y = (a0.y + a1.y) * ic;
                a0.z = (a0.z + a1.z) * ic;
                a0.w = (a0.w + a1.w) * ic;
            }
            *(float4*)(meanS + lrow * MST + lane * 4) = a0;
        }
    }
    __syncthreads();

    // ---- phase 2: GEMM C = [mean|x] @ W' (fp16-split, 3-product) ----
    int wm = wid & 3;
    int wn = wid >> 2;

    float acc[2][8][4];
#pragma unroll
    for (int a = 0; a < 2; a++)
#pragma unroll
        for (int b = 0; b < 8; b++)
#pragma unroll
            for (int c = 0; c < 4; c++) acc[a][b][c] = 0.f;

    uint32_t ahB = smem_u32(Ah), alB = smem_u32(Al);
    uint32_t bhB = smem_u32(Bh), blB = smem_u32(Bl);

    int a_row = wm * 32 + (lane & 7) + ((lane >> 3) & 1) * 8;
    int a_col = (lane >> 4) * 8;
    int b_row = wn * 64 + (lane & 7) + (lane >> 4) * 8;
    int b_col = ((lane >> 3) & 1) * 8;

    int frow = tid >> 1;
    int fcol = (tid & 1) * 16;

    for (int kb = 0; kb < 8; kb++) {
        // ---- fill A tile (fp32 / decoded bf16 -> fp16 hi/lo split) ----
        {
            int kc = (kb & 3) * 32;
            int gr = row0 + frow;
            __half* ah = Ah + frow * AST + fcol;
            __half* al = Al + frow * AST + fcol;
            const uint2* px = (const uint2*)(xin_t + (size_t)gr * DD + kc + fcol);
#pragma unroll
            for (int i = 0; i < 4; i++) {
                float4 v;
                if (kb < 4) {
                    v = *(const float4*)(meanS + frow * MST + kc + fcol + i * 4);
                } else if (gr < n) {
                    uint2 hb = px[i];
                    v.x = __uint_as_float(hb.x << 16);
                    v.y = __uint_as_float(hb.x & 0xffff0000u);
                    v.z = __uint_as_float(hb.y << 16);
                    v.w = __uint_as_float(hb.y & 0xffff0000u);
                } else {
                    v = make_float4(0.f, 0.f, 0.f, 0.f);
                }
                __half hx = __float2half_rn(v.x), hy = __float2half_rn(v.y);
                __half hz = __float2half_rn(v.z), hw = __float2half_rn(v.w);
                *(half2*)(ah + i * 4)     = __halves2half2(hx, hy);
                *(half2*)(ah + i * 4 + 2) = __halves2half2(hz, hw);
                *(half2*)(al + i * 4)     = __halves2half2(
                    __float2half_rn(v.x - __half2float(hx)),
                    __float2half_rn(v.y - __half2float(hy)));
                *(half2*)(al + i * 4 + 2) = __halves2half2(
                    __float2half_rn(v.z - __half2float(hz)),
                    __float2half_rn(v.w - __half2float(hw)));
            }
        }
        // ---- fill B tile (pre-split fp16 weights) ----
        {
            int bn = tid >> 1;
            size_t goff = (size_t)bn * 256 + kb * 32 + fcol;
            const int4* gh = (const int4*)(whi + goff);
            const int4* gl = (const int4*)(wlo + goff);
            int4* sh = (int4*)(Bh + bn * AST + fcol);
            int4* sl = (int4*)(Bl + bn * AST + fcol);
            sh[0] = gh[0]; sh[1] = gh[1];
            sl[0] = gl[0]; sl[1] = gl[1];
        }
        __syncthreads();

#pragma unroll
        for (int ks = 0; ks < 2; ks++) {
            int k0 = ks * 16;
            uint32_t ah[2][4], al2[2][4], bf[16];
#pragma unroll
            for (int mt = 0; mt < 2; mt++)
                ldsm4(ah[mt], ahB + ((a_row + mt * 16) * AST + a_col + k0) * 2);
#pragma unroll
            for (int p = 0; p < 4; p++)
                ldsm4(&bf[p * 4], bhB + ((b_row + p * 16) * AST + b_col + k0) * 2);
            // P1: ah x bh
#pragma unroll
            for (int mt = 0; mt < 2; mt++)
#pragma unroll
                for (int p = 0; p < 4; p++) {
                    mma16816(acc[mt][p * 2 + 0], ah[mt], &bf[p * 4 + 0]);
                    mma16816(acc[mt][p * 2 + 1], ah[mt], &bf[p * 4 + 2]);
                }
#pragma unroll
            for (int mt = 0; mt < 2; mt++)
                ldsm4(al2[mt], alB + ((a_row + mt * 16) * AST + a_col + k0) * 2);
            // P2: al x bh
#pragma unroll
            for (int mt = 0; mt < 2; mt++)
#pragma unroll
                for (int p = 0; p < 4; p++) {
                    mma16816(acc[mt][p * 2 + 0], al2[mt], &bf[p * 4 + 0]);
                    mma16816(acc[mt][p * 2 + 1], al2[mt], &bf[p * 4 + 2]);
                }
#pragma unroll
            for (int p = 0; p < 4; p++)
                ldsm4(&bf[p * 4], blB + ((b_row + p * 16) * AST + b_col + k0) * 2);
            // P3: ah x bl
#pragma unroll
            for (int mt = 0; mt < 2; mt++)
#pragma unroll
                for (int p = 0; p < 4; p++) {
                    mma16816(acc[mt][p * 2 + 0], ah[mt], &bf[p * 4 + 0]);
                    mma16816(acc[mt][p * 2 + 1], ah[mt], &bf[p * 4 + 2]);
                }
        }
        __syncthreads();
    }

    // ---- epilogue: bias + relu -> bf16 stores ----
#pragma unroll
    for (int mt = 0; mt < 2; mt++) {
#pragma unroll
        for (int rr = 0; rr < 2; rr++) {
            int row = row0 + wm * 32 + mt * 16 + (lane >> 2) + rr * 8;
            if (row >= n) continue;
#pragma unroll
            for (int nt = 0; nt < 8; nt++) {
                int col = wn * 64 + nt * 8 + (lane & 3) * 2;
                float vx = fmaxf(acc[mt][nt][rr * 2 + 0] + __ldg(&bias_t[col + 0]), 0.f);
                float vy = fmaxf(acc[mt][nt][rr * 2 + 1] + __ldg(&bias_t[col + 1]), 0.f);
                *(uint32_t*)(yout_t + (size_t)row * DD + col) = bf2(vx, vy);
            }
        }
    }
}

// ---------------- pooling + head ----------------
#define ROWS_PB 256
__global__ void pool_both_kernel(const __nv_bfloat16* __restrict__ x,
                                 const int* __restrict__ ba, const int* __restrict__ bb,
                                 int n, int pblocks) {
    int t = (blockIdx.x >= pblocks);
    int blk = t ? blockIdx.x - pblocks : blockIdx.x;
    const __nv_bfloat16* x_t = x + (size_t)t * NN * DD;
    const int* batch = t ? bb : ba;
    float* pool = &g_pool[t][0][0];
    int* pcnt = g_pcnt[t];

    int c = threadIdx.x;
    int r0 = blk * ROWS_PB;
    if (r0 >= n) return;
    int r1 = min(r0 + ROWS_PB, n);
    float acc = 0.f;
    int cnt = 0;
    int gcur = batch[r0];
    for (int r = r0; r < r1; r++) {
        int g = batch[r];
        if (g != gcur) {
            atomicAdd(&pool[(size_t)gcur * DD + c], acc);
            if (c == 0) atomicAdd(&pcnt[gcur], cnt);
            acc = 0.f; cnt = 0; gcur = g;
        }
        unsigned short h = *(const unsigned short*)(x_t + (size_t)r * DD + c);
        acc += __uint_as_float(((uint32_t)h) << 16);
        cnt++;
    }
    atomicAdd(&pool[(size_t)gcur * DD + c], acc);
    if (c == 0) atomicAdd(&pcnt[gcur], cnt);
}

__global__ void final_kernel(const float* __restrict__ linW, const float* __restrict__ linb,
                             float* __restrict__ out) {
    int t32 = threadIdx.x;
    if (t32 >= GG * OUTD) return;
    int g = t32 / OUTD;
    int o = t32 % OUTD;
    float s = linb[o];
    for (int t = 0; t < 2; t++) {
        float ic = 1.0f / fmaxf((float)g_pcnt[t][g], 1.0f);
        const float* p = &g_pool[t][g][0];
        for (int c = 0; c < DD; c++)
            s += p[c] * ic * linW[(t * DD + c) * OUTD + o];
    }
    out[g * OUTD + o] = s;
}

// ---------------- launch ----------------
extern "C" void kernel_launch(void* const* d_in, const int* in_sizes, int n_in,
                              void* d_out, int out_size) {
    const float* x_void   = (const float*)d_in[0];
    const float* x_vessel = (const float*)d_in[1];
    const float* Wl   = (const float*)d_in[2];
    const float* bl   = (const float*)d_in[3];
    const float* Wr   = (const float*)d_in[4];
    const float* linW = (const float*)d_in[5];
    const float* linb = (const float*)d_in[6];
    const int* edge_void   = (const int*)d_in[7];
    const int* edge_vessel = (const int*)d_in[8];
    const int* batch_void   = (const int*)d_in[9];
    const int* batch_vessel = (const int*)d_in[10];

    const int n = in_sizes[9];
    const int E = in_sizes[7] / 2;

    __nv_bfloat16* xP;
    __half *whiP, *wloP;
    cudaGetSymbolAddress((void**)&xP, g_x);
    cudaGetSymbolAddress((void**)&whiP, g_wT_hi);
    cudaGetSymbolAddress((void**)&wloP, g_wT_lo);

    cudaFuncSetAttribute(layer_kernel,
                         cudaFuncAttributeMaxDynamicSharedMemorySize, SMEM_LAYER);

    // setup
    zero_all_kernel<<<128, 256>>>();
    count_both_kernel<<<1024, 256>>>(edge_void + E, edge_vessel + E, E);
    scan_both_kernel<<<2, 1024>>>(n);
    fill_both_kernel<<<1024, 256>>>(edge_void, edge_vessel, E);
    {
        dim3 g(128, 6);
        wprep_all_kernel<<<g, 128>>>(Wl, Wr);
    }
    conv_kernel<<<512, 256>>>(x_void, x_vessel, n);

    const int tiles = (n + 127) / 128;
    const size_t PP = (size_t)2 * NN * DD;   // pingpong stride

    for (int l = 0; l < LL; l++) {
        int pin = l & 1;                     // 0,1,0
        int pout = 1 - pin;                  // 1,0,1
        layer_kernel<<<2 * tiles, 256, SMEM_LAYER>>>(
            xP + pin * PP, xP + pout * PP,
            whiP + (size_t)l * 2 * 32768, wloP + (size_t)l * 2 * 32768,
            bl + (size_t)l * 2 * DD, n, tiles);
    }

    // pooling reads ping 1 (output of layer 2)
    int pblocks = (n + ROWS_PB - 1) / ROWS_PB;
    pool_both_kernel<<<2 * pblocks, DD>>>(xP + PP, batch_void, batch_vessel, n, pblocks);
    final_kernel<<<1, 32>>>(linW, linb, (float*)d_out);
}